// round 1
// baseline (speedup 1.0000x reference)
#include <cuda_runtime.h>
#include <math.h>

// Problem constants
#define BATCH      2048
#define NODES      12
#define NTOK       (BATCH * NODES)     // 24576
#define D          128
#define F          512
#define NHEAD      4
#define DH         32
#define SCALE      0.17677669529663687f  // 1/sqrt(32)

// ---------------- scratch (device globals; no allocation) ----------------
__device__ float g_x  [NTOK * D];
__device__ float g_h  [NTOK * D];
__device__ float g_q  [NTOK * D];
__device__ float g_k  [NTOK * D];
__device__ float g_v  [NTOK * D];
__device__ float g_msg[NTOK * D];
__device__ float g_t  [NTOK * F];

__device__ __forceinline__ float gelu_exact(float x) {
    return 0.5f * x * (1.0f + erff(x * 0.7071067811865476f));
}

// ---------------- init: build x from patch/band/summary tokens ----------------
__global__ void init_x_kernel(const float* __restrict__ patch,
                              const float* __restrict__ band,
                              const float* __restrict__ summ,
                              float* __restrict__ x) {
    int idx = blockIdx.x * blockDim.x + threadIdx.x;
    if (idx >= NTOK * D) return;
    int d    = idx & (D - 1);
    int row  = idx >> 7;
    int node = row % NODES;
    int b    = row / NODES;
    float val;
    if (node < 6)       val = patch[(b * 6 + node) * D + d];
    else if (node < 11) val = band [(b * 5 + (node - 6)) * D + d];
    else                val = summ[d];
    x[idx] = val;
}

// ---------------- LayerNorm: one warp per row (D=128) ----------------
__global__ void ln_kernel(const float* __restrict__ in, float* __restrict__ out,
                          const float* __restrict__ s, const float* __restrict__ b) {
    int row  = blockIdx.x * 4 + (threadIdx.x >> 5);
    int lane = threadIdx.x & 31;
    const float* rp = in + (size_t)row * D;
    float v[4];
    float sum = 0.f;
#pragma unroll
    for (int i = 0; i < 4; i++) { v[i] = rp[lane + 32 * i]; sum += v[i]; }
#pragma unroll
    for (int o = 16; o; o >>= 1) sum += __shfl_xor_sync(0xffffffffu, sum, o);
    float mu = sum * (1.0f / 128.0f);
    float sq = 0.f;
#pragma unroll
    for (int i = 0; i < 4; i++) { float c = v[i] - mu; sq += c * c; }
#pragma unroll
    for (int o = 16; o; o >>= 1) sq += __shfl_xor_sync(0xffffffffu, sq, o);
    float inv = rsqrtf(sq * (1.0f / 128.0f) + 1e-5f);
#pragma unroll
    for (int i = 0; i < 4; i++) {
        int d = lane + 32 * i;
        out[(size_t)row * D + d] = (v[i] - mu) * inv * s[d] + b[d];
    }
}

// ---------------- Tiled SGEMM: C = epilogue(A[MxK] @ W[KxN] + bias) ----------------
// mode 0: C = A@W + bias
// mode 1: C = resid + A@W + bias
// mode 2: C = gelu(A@W + bias)
#define BM 64
#define BN 64
#define BK 16
__global__ __launch_bounds__(256) void gemm_kernel(
    const float* __restrict__ A, const float* __restrict__ W,
    const float* __restrict__ bias, float* __restrict__ C,
    const float* __restrict__ resid, int M, int N, int K, int mode) {
    __shared__ float As[BK][BM + 4];
    __shared__ float Ws[BK][BN + 4];
    int bm = blockIdx.y * BM;
    int bn = blockIdx.x * BN;
    int tid = threadIdx.x;
    int tx = tid & 15;       // 0..15 -> N
    int ty = tid >> 4;       // 0..15 -> M
    float acc[4][4] = {};
    for (int k0 = 0; k0 < K; k0 += BK) {
        // A tile: BM x BK
#pragma unroll
        for (int t = tid; t < BM * BK; t += 256) {
            int r = t / BK, c = t % BK;
            As[c][r] = A[(size_t)(bm + r) * K + k0 + c];
        }
        // W tile: BK x BN
#pragma unroll
        for (int t = tid; t < BK * BN; t += 256) {
            int r = t / BN, c = t % BN;
            Ws[r][c] = W[(size_t)(k0 + r) * N + bn + c];
        }
        __syncthreads();
#pragma unroll
        for (int kk = 0; kk < BK; kk++) {
            float a[4], w[4];
#pragma unroll
            for (int i = 0; i < 4; i++) a[i] = As[kk][ty * 4 + i];
#pragma unroll
            for (int j = 0; j < 4; j++) w[j] = Ws[kk][tx * 4 + j];
#pragma unroll
            for (int i = 0; i < 4; i++)
#pragma unroll
                for (int j = 0; j < 4; j++) acc[i][j] = fmaf(a[i], w[j], acc[i][j]);
        }
        __syncthreads();
    }
#pragma unroll
    for (int i = 0; i < 4; i++) {
        int row = bm + ty * 4 + i;
#pragma unroll
        for (int j = 0; j < 4; j++) {
            int col = bn + tx * 4 + j;
            float val = acc[i][j] + bias[col];
            size_t off = (size_t)row * N + col;
            if (mode == 1)      val += resid[off];
            else if (mode == 2) val  = gelu_exact(val);
            C[off] = val;
        }
    }
}

// ---------------- dense 12-node attention, one block per batch ----------------
__global__ void attn_kernel(const float* __restrict__ q, const float* __restrict__ k,
                            const float* __restrict__ v,
                            const float* __restrict__ edge_bias, // 9*4 floats for layer l
                            float* __restrict__ msg) {
    __shared__ float sq[NODES * D], sk[NODES * D], sv[NODES * D];
    __shared__ float seb[36];
    int b = blockIdx.x;
    size_t base = (size_t)b * NODES * D;
    for (int i = threadIdx.x; i < NODES * D; i += 64) {
        sq[i] = q[base + i];
        sk[i] = k[base + i];
        sv[i] = v[base + i];
    }
    if (threadIdx.x < 36) seb[threadIdx.x] = edge_bias[threadIdx.x];
    __syncthreads();
    int t = threadIdx.x;
    if (t < NODES * NHEAD) {
        int dst = t >> 2, h = t & 3;
        int kd = dst < 6 ? 0 : (dst < 11 ? 1 : 2);
        float logits[NODES];
        float mx = -1e30f;
        const float* qp = &sq[dst * D + h * DH];
#pragma unroll
        for (int j = 0; j < NODES; j++) {
            int ks = j < 6 ? 0 : (j < 11 ? 1 : 2);
            const float* kp = &sk[j * D + h * DH];
            float dot = 0.f;
#pragma unroll
            for (int d = 0; d < DH; d++) dot = fmaf(qp[d], kp[d], dot);
            float lg = dot * SCALE + seb[(ks * 3 + kd) * NHEAD + h];
            logits[j] = lg;
            mx = fmaxf(mx, lg);
        }
        float z = 0.f;
#pragma unroll
        for (int j = 0; j < NODES; j++) { logits[j] = expf(logits[j] - mx); z += logits[j]; }
        float inv = 1.0f / z;
        float out[DH] = {};
#pragma unroll
        for (int j = 0; j < NODES; j++) {
            float a = logits[j] * inv;
            const float* vp = &sv[j * D + h * DH];
#pragma unroll
            for (int d = 0; d < DH; d++) out[d] = fmaf(a, vp[d], out[d]);
        }
#pragma unroll
        for (int d = 0; d < DH; d++) msg[base + dst * D + h * DH + d] = out[d];
    }
}

// ---------------- final: gate/pool + summary concat + proj + LN + gelu ----------------
__global__ void final_kernel(const float* __restrict__ x,
                             const float* __restrict__ gate_w, const float* __restrict__ gate_b,
                             const float* __restrict__ proj_w, const float* __restrict__ proj_b,
                             const float* __restrict__ pln_s, const float* __restrict__ pln_b,
                             float* __restrict__ out) {
    __shared__ float sx[NODES * D];
    __shared__ float sgate[NODES];
    __shared__ float comb[2 * D];
    __shared__ float red[4];
    int b = blockIdx.x, tid = threadIdx.x; // 128 threads
    for (int i = tid; i < NODES * D; i += 128) sx[i] = x[(size_t)b * NODES * D + i];
    __syncthreads();
    if (tid < NODES) {
        float acc = gate_b[0];
#pragma unroll 8
        for (int d = 0; d < D; d++) acc = fmaf(sx[tid * D + d], gate_w[d], acc);
        sgate[tid] = 1.0f / (1.0f + expf(-acc));
    }
    __syncthreads();
    float pooled = 0.f;
#pragma unroll
    for (int n = 0; n < NODES; n++) pooled = fmaf(sx[n * D + tid], sgate[n], pooled);
    comb[tid]     = sx[11 * D + tid]; // summary node row
    comb[D + tid] = pooled;
    __syncthreads();
    float y = proj_b[tid];
#pragma unroll 8
    for (int c = 0; c < 2 * D; c++) y = fmaf(comb[c], proj_w[c * D + tid], y);
    // LayerNorm across the 128 outputs (one per thread)
    float sum = y;
#pragma unroll
    for (int o = 16; o; o >>= 1) sum += __shfl_xor_sync(0xffffffffu, sum, o);
    if ((tid & 31) == 0) red[tid >> 5] = sum;
    __syncthreads();
    float mu = (red[0] + red[1] + red[2] + red[3]) * (1.0f / 128.0f);
    float c0 = y - mu;
    float cs = c0 * c0;
#pragma unroll
    for (int o = 16; o; o >>= 1) cs += __shfl_xor_sync(0xffffffffu, cs, o);
    __syncthreads();
    if ((tid & 31) == 0) red[tid >> 5] = cs;
    __syncthreads();
    float var = (red[0] + red[1] + red[2] + red[3]) * (1.0f / 128.0f);
    float yn = c0 * rsqrtf(var + 1e-5f) * pln_s[tid] + pln_b[tid];
    out[(size_t)b * D + tid] = gelu_exact(yn);
}

// ---------------- host orchestration ----------------
extern "C" void kernel_launch(void* const* d_in, const int* in_sizes, int n_in,
                              void* d_out, int out_size) {
    const float* patch   = (const float*)d_in[0];
    const float* band    = (const float*)d_in[1];
    const float* summ    = (const float*)d_in[2];
    const float* ln1_s   = (const float*)d_in[3];
    const float* ln1_b   = (const float*)d_in[4];
    const float* wq      = (const float*)d_in[5];
    const float* bq      = (const float*)d_in[6];
    const float* wk      = (const float*)d_in[7];
    const float* bk      = (const float*)d_in[8];
    const float* wv      = (const float*)d_in[9];
    const float* bv      = (const float*)d_in[10];
    const float* wo      = (const float*)d_in[11];
    const float* bo      = (const float*)d_in[12];
    const float* edge_b  = (const float*)d_in[13];
    const float* ln2_s   = (const float*)d_in[14];
    const float* ln2_b   = (const float*)d_in[15];
    const float* w1      = (const float*)d_in[16];
    const float* b1      = (const float*)d_in[17];
    const float* w2      = (const float*)d_in[18];
    const float* b2      = (const float*)d_in[19];
    const float* gate_w  = (const float*)d_in[20];
    const float* gate_b  = (const float*)d_in[21];
    const float* proj_w  = (const float*)d_in[22];
    const float* proj_b  = (const float*)d_in[23];
    const float* pln_s   = (const float*)d_in[24];
    const float* pln_b   = (const float*)d_in[25];
    float* out = (float*)d_out;

    float *x, *h, *q, *k, *v, *msg, *t;
    cudaGetSymbolAddress((void**)&x,   g_x);
    cudaGetSymbolAddress((void**)&h,   g_h);
    cudaGetSymbolAddress((void**)&q,   g_q);
    cudaGetSymbolAddress((void**)&k,   g_k);
    cudaGetSymbolAddress((void**)&v,   g_v);
    cudaGetSymbolAddress((void**)&msg, g_msg);
    cudaGetSymbolAddress((void**)&t,   g_t);

    // build x
    {
        int total = NTOK * D;
        init_x_kernel<<<(total + 255) / 256, 256>>>(patch, band, summ, x);
    }

    dim3 gemm_threads(256);
    dim3 grid_d  (D / BN, NTOK / BM);  // N=128
    dim3 grid_f  (F / BN, NTOK / BM);  // N=512

    for (int l = 0; l < 2; l++) {
        const float* wq_l = wq + (size_t)l * D * D;
        const float* wk_l = wk + (size_t)l * D * D;
        const float* wv_l = wv + (size_t)l * D * D;
        const float* wo_l = wo + (size_t)l * D * D;
        const float* w1_l = w1 + (size_t)l * D * F;
        const float* w2_l = w2 + (size_t)l * F * D;

        ln_kernel<<<NTOK / 4, 128>>>(x, h, ln1_s + l * D, ln1_b + l * D);
        gemm_kernel<<<grid_d, gemm_threads>>>(h, wq_l, bq + l * D, q, nullptr, NTOK, D, D, 0);
        gemm_kernel<<<grid_d, gemm_threads>>>(h, wk_l, bk + l * D, k, nullptr, NTOK, D, D, 0);
        gemm_kernel<<<grid_d, gemm_threads>>>(h, wv_l, bv + l * D, v, nullptr, NTOK, D, D, 0);
        attn_kernel<<<BATCH, 64>>>(q, k, v, edge_b + l * 36, msg);
        gemm_kernel<<<grid_d, gemm_threads>>>(msg, wo_l, bo + l * D, x, x, NTOK, D, D, 1);
        ln_kernel<<<NTOK / 4, 128>>>(x, h, ln2_s + l * D, ln2_b + l * D);
        gemm_kernel<<<grid_f, gemm_threads>>>(h, w1_l, b1 + l * F, t, nullptr, NTOK, F, D, 2);
        gemm_kernel<<<grid_d, gemm_threads>>>(t, w2_l, b2 + l * D, x, x, NTOK, D, F, 1);
    }

    final_kernel<<<BATCH, 128>>>(x, gate_w, gate_b, proj_w, proj_b, pln_s, pln_b, out);
}

// round 2
// speedup vs baseline: 1.2543x; 1.2543x over previous
#include <cuda_runtime.h>
#include <math.h>
#include <stdint.h>

// Problem constants
#define BATCH      2048
#define NODES      12
#define NTOK       (BATCH * NODES)     // 24576
#define D          128
#define F          512
#define NHEAD      4
#define DH         32
#define SCALE      0.17677669529663687f  // 1/sqrt(32)

// ---------------- scratch (device globals; no allocation) ----------------
__device__ float g_x   [NTOK * D];
__device__ float g_h   [NTOK * D];
__device__ float g_qkv [NTOK * 384];
__device__ float g_msg [NTOK * D];
__device__ float g_t   [NTOK * F];
__device__ float g_wqkv[2 * D * 384];
__device__ float g_bqkv[2 * 384];

__device__ __forceinline__ float gelu_exact(float x) {
    return 0.5f * x * (1.0f + erff(x * 0.7071067811865476f));
}

__device__ __forceinline__ uint32_t f2tf32(float x) {
    uint32_t r;
    asm("cvt.rna.tf32.f32 %0, %1;" : "=r"(r) : "f"(x));
    return r;
}
__device__ __forceinline__ void split_tf32(float x, uint32_t& h, uint32_t& l) {
    h = f2tf32(x);
    l = f2tf32(x - __uint_as_float(h));
}
__device__ __forceinline__ void mma_tf32(float* c, const uint32_t* a, uint32_t b0, uint32_t b1) {
    asm volatile(
        "mma.sync.aligned.m16n8k8.row.col.f32.tf32.tf32.f32 "
        "{%0,%1,%2,%3}, {%4,%5,%6,%7}, {%8,%9}, {%0,%1,%2,%3};"
        : "+f"(c[0]), "+f"(c[1]), "+f"(c[2]), "+f"(c[3])
        : "r"(a[0]), "r"(a[1]), "r"(a[2]), "r"(a[3]), "r"(b0), "r"(b1));
}

// ---------------- init: build x from patch/band/summary tokens ----------------
__global__ void init_x_kernel(const float* __restrict__ patch,
                              const float* __restrict__ band,
                              const float* __restrict__ summ,
                              float* __restrict__ x) {
    int idx = blockIdx.x * blockDim.x + threadIdx.x;
    if (idx >= NTOK * D) return;
    int d    = idx & (D - 1);
    int row  = idx >> 7;
    int node = row % NODES;
    int b    = row / NODES;
    float val;
    if (node < 6)       val = patch[(b * 6 + node) * D + d];
    else if (node < 11) val = band [(b * 5 + (node - 6)) * D + d];
    else                val = summ[d];
    x[idx] = val;
}

// ---------------- pack QKV weights/biases into fused [K=128][N=384] ----------------
__global__ void pack_qkv_kernel(const float* __restrict__ wq, const float* __restrict__ wk,
                                const float* __restrict__ wv,
                                const float* __restrict__ bq, const float* __restrict__ bk,
                                const float* __restrict__ bv,
                                float* __restrict__ wqkv, float* __restrict__ bqkv) {
    int idx = blockIdx.x * 256 + threadIdx.x;
    if (idx < 2 * D * 384) {
        int l = idx / (D * 384);
        int r = idx % (D * 384);
        int k = r / 384, n = r % 384;
        const float* src = (n < 128) ? wq : ((n < 256) ? wk : wv);
        wqkv[idx] = src[(size_t)l * D * D + k * D + (n & 127)];
    }
    if (idx < 2 * 384) {
        int l = idx / 384, n = idx % 384;
        const float* sb = (n < 128) ? bq : ((n < 256) ? bk : bv);
        bqkv[idx] = sb[l * D + (n & 127)];
    }
}

// ---------------- LayerNorm: one warp per row (D=128) ----------------
__global__ void ln_kernel(const float* __restrict__ in, float* __restrict__ out,
                          const float* __restrict__ s, const float* __restrict__ b) {
    int row  = blockIdx.x * 4 + (threadIdx.x >> 5);
    int lane = threadIdx.x & 31;
    const float* rp = in + (size_t)row * D;
    float v[4];
    float sum = 0.f;
#pragma unroll
    for (int i = 0; i < 4; i++) { v[i] = rp[lane + 32 * i]; sum += v[i]; }
#pragma unroll
    for (int o = 16; o; o >>= 1) sum += __shfl_xor_sync(0xffffffffu, sum, o);
    float mu = sum * (1.0f / 128.0f);
    float sq = 0.f;
#pragma unroll
    for (int i = 0; i < 4; i++) { float c = v[i] - mu; sq += c * c; }
#pragma unroll
    for (int o = 16; o; o >>= 1) sq += __shfl_xor_sync(0xffffffffu, sq, o);
    float inv = rsqrtf(sq * (1.0f / 128.0f) + 1e-5f);
#pragma unroll
    for (int i = 0; i < 4; i++) {
        int d = lane + 32 * i;
        out[(size_t)row * D + d] = (v[i] - mu) * inv * s[d] + b[d];
    }
}

// ---------------- tf32x3 tensor-core GEMM ----------------
// C[M,N] = epilogue(A[M,K] @ W[K,N] + bias); mode 0 plain, 1 +resid, 2 gelu
// BM=64, BN=128, BK=8, 256 threads (8 warps, 2x4 grid of 32x32 warp tiles)
__global__ __launch_bounds__(256) void tgemm_kernel(
    const float* __restrict__ A, const float* __restrict__ W,
    const float* __restrict__ bias, float* __restrict__ C,
    const float* __restrict__ resid, int M, int N, int K, int mode) {
    __shared__ uint32_t Ah[2][8][72], Al[2][8][72];     // [k][m], stride 72 (== 8 mod 32)
    __shared__ uint32_t Wh[2][8][136], Wl[2][8][136];   // [k][n], stride 136 (== 8 mod 32)

    const int bm = blockIdx.y * 64;
    const int bn = blockIdx.x * 128;
    const int tid  = threadIdx.x;
    const int lane = tid & 31;
    const int wid  = tid >> 5;
    const int wm = (wid >> 2) << 5;    // 0 / 32
    const int wn = (wid & 3) << 5;     // 0..96
    const int g = lane >> 2, t = lane & 3;

    // gmem load assignment
    const int ar = tid >> 2;           // m row 0..63
    const int ac = (tid & 3) << 1;     // k 0,2,4,6
    const int wr = tid >> 5;           // k 0..7
    const int wc = (tid & 31) << 2;    // n (x4)

    const float* Ap = A + (size_t)(bm + ar) * K + ac;
    const float* Wp = W + (size_t)wr * N + bn + wc;

    float acc[2][4][4];
#pragma unroll
    for (int i = 0; i < 2; i++)
#pragma unroll
        for (int j = 0; j < 4; j++)
#pragma unroll
            for (int c = 0; c < 4; c++) acc[i][j][c] = 0.f;

    float2 pa = *(const float2*)Ap;
    float4 pw = *(const float4*)Wp;

    // stage 0 -> buf 0
    {
        uint32_t h, l;
        split_tf32(pa.x, h, l); Ah[0][ac][ar] = h;     Al[0][ac][ar] = l;
        split_tf32(pa.y, h, l); Ah[0][ac + 1][ar] = h; Al[0][ac + 1][ar] = l;
        split_tf32(pw.x, h, l); Wh[0][wr][wc] = h;     Wl[0][wr][wc] = l;
        split_tf32(pw.y, h, l); Wh[0][wr][wc + 1] = h; Wl[0][wr][wc + 1] = l;
        split_tf32(pw.z, h, l); Wh[0][wr][wc + 2] = h; Wl[0][wr][wc + 2] = l;
        split_tf32(pw.w, h, l); Wh[0][wr][wc + 3] = h; Wl[0][wr][wc + 3] = l;
    }
    __syncthreads();

    const int nstage = K >> 3;
    int buf = 0;
    for (int s = 0; s < nstage; s++) {
        if (s + 1 < nstage) {
            pa = *(const float2*)(Ap + (s + 1) * 8);
            pw = *(const float4*)(Wp + (size_t)(s + 1) * 8 * N);
        }
        uint32_t ah[2][4], al[2][4], bh[4][2], bl[4][2];
#pragma unroll
        for (int mi = 0; mi < 2; mi++) {
            int m0 = wm + mi * 16 + g;
            ah[mi][0] = Ah[buf][t][m0];     ah[mi][1] = Ah[buf][t][m0 + 8];
            ah[mi][2] = Ah[buf][t + 4][m0]; ah[mi][3] = Ah[buf][t + 4][m0 + 8];
            al[mi][0] = Al[buf][t][m0];     al[mi][1] = Al[buf][t][m0 + 8];
            al[mi][2] = Al[buf][t + 4][m0]; al[mi][3] = Al[buf][t + 4][m0 + 8];
        }
#pragma unroll
        for (int ni = 0; ni < 4; ni++) {
            int n0 = wn + ni * 8 + g;
            bh[ni][0] = Wh[buf][t][n0]; bh[ni][1] = Wh[buf][t + 4][n0];
            bl[ni][0] = Wl[buf][t][n0]; bl[ni][1] = Wl[buf][t + 4][n0];
        }
#pragma unroll
        for (int mi = 0; mi < 2; mi++)
#pragma unroll
            for (int ni = 0; ni < 4; ni++) {
                mma_tf32(acc[mi][ni], ah[mi], bh[ni][0], bh[ni][1]);
                mma_tf32(acc[mi][ni], al[mi], bh[ni][0], bh[ni][1]);
                mma_tf32(acc[mi][ni], ah[mi], bl[ni][0], bl[ni][1]);
            }
        if (s + 1 < nstage) {
            int nb = buf ^ 1;
            uint32_t h, l;
            split_tf32(pa.x, h, l); Ah[nb][ac][ar] = h;     Al[nb][ac][ar] = l;
            split_tf32(pa.y, h, l); Ah[nb][ac + 1][ar] = h; Al[nb][ac + 1][ar] = l;
            split_tf32(pw.x, h, l); Wh[nb][wr][wc] = h;     Wl[nb][wr][wc] = l;
            split_tf32(pw.y, h, l); Wh[nb][wr][wc + 1] = h; Wl[nb][wr][wc + 1] = l;
            split_tf32(pw.z, h, l); Wh[nb][wr][wc + 2] = h; Wl[nb][wr][wc + 2] = l;
            split_tf32(pw.w, h, l); Wh[nb][wr][wc + 3] = h; Wl[nb][wr][wc + 3] = l;
            __syncthreads();
            buf = nb;
        }
    }

    // epilogue
#pragma unroll
    for (int mi = 0; mi < 2; mi++) {
        int r0 = bm + wm + mi * 16 + g;
#pragma unroll
        for (int ni = 0; ni < 4; ni++) {
            int col = bn + wn + ni * 8 + 2 * t;
            float b0 = bias[col], b1 = bias[col + 1];
            float v0 = acc[mi][ni][0] + b0, v1 = acc[mi][ni][1] + b1;
            float v2 = acc[mi][ni][2] + b0, v3 = acc[mi][ni][3] + b1;
            size_t o0 = (size_t)r0 * N + col;
            size_t o1 = (size_t)(r0 + 8) * N + col;
            if (mode == 1) {
                v0 += resid[o0]; v1 += resid[o0 + 1];
                v2 += resid[o1]; v3 += resid[o1 + 1];
            } else if (mode == 2) {
                v0 = gelu_exact(v0); v1 = gelu_exact(v1);
                v2 = gelu_exact(v2); v3 = gelu_exact(v3);
            }
            *(float2*)&C[o0] = make_float2(v0, v1);
            *(float2*)&C[o1] = make_float2(v2, v3);
        }
    }
}

// ---------------- dense 12-node attention, one block per batch ----------------
// reads fused qkv buffer: row stride 384, q at +0, k at +128, v at +256
__global__ void attn_kernel(const float* __restrict__ qkv,
                            const float* __restrict__ edge_bias,
                            float* __restrict__ msg) {
    __shared__ float sq[NODES * D], sk[NODES * D], sv[NODES * D];
    __shared__ float seb[36];
    int b = blockIdx.x;
    size_t base  = (size_t)b * NODES * 384;
    size_t obase = (size_t)b * NODES * D;
    for (int i = threadIdx.x; i < NODES * D; i += 64) {
        int node = i >> 7, col = i & 127;
        sq[i] = qkv[base + node * 384 + col];
        sk[i] = qkv[base + node * 384 + 128 + col];
        sv[i] = qkv[base + node * 384 + 256 + col];
    }
    if (threadIdx.x < 36) seb[threadIdx.x] = edge_bias[threadIdx.x];
    __syncthreads();
    int tt = threadIdx.x;
    if (tt < NODES * NHEAD) {
        int dst = tt >> 2, h = tt & 3;
        int kd = dst < 6 ? 0 : (dst < 11 ? 1 : 2);
        float logits[NODES];
        float mx = -1e30f;
        const float* qp = &sq[dst * D + h * DH];
#pragma unroll
        for (int j = 0; j < NODES; j++) {
            int ks = j < 6 ? 0 : (j < 11 ? 1 : 2);
            const float* kp = &sk[j * D + h * DH];
            float dot = 0.f;
#pragma unroll
            for (int d = 0; d < DH; d++) dot = fmaf(qp[d], kp[d], dot);
            float lg = dot * SCALE + seb[(ks * 3 + kd) * NHEAD + h];
            logits[j] = lg;
            mx = fmaxf(mx, lg);
        }
        float z = 0.f;
#pragma unroll
        for (int j = 0; j < NODES; j++) { logits[j] = expf(logits[j] - mx); z += logits[j]; }
        float inv = 1.0f / z;
        float out[DH] = {};
#pragma unroll
        for (int j = 0; j < NODES; j++) {
            float a = logits[j] * inv;
            const float* vp = &sv[j * D + h * DH];
#pragma unroll
            for (int d = 0; d < DH; d++) out[d] = fmaf(a, vp[d], out[d]);
        }
#pragma unroll
        for (int d = 0; d < DH; d++) msg[obase + dst * D + h * DH + d] = out[d];
    }
}

// ---------------- final: gate/pool + summary concat + proj + LN + gelu ----------------
__global__ void final_kernel(const float* __restrict__ x,
                             const float* __restrict__ gate_w, const float* __restrict__ gate_b,
                             const float* __restrict__ proj_w, const float* __restrict__ proj_b,
                             const float* __restrict__ pln_s, const float* __restrict__ pln_b,
                             float* __restrict__ out) {
    __shared__ float sx[NODES * D];
    __shared__ float sgate[NODES];
    __shared__ float comb[2 * D];
    __shared__ float red[4];
    int b = blockIdx.x, tid = threadIdx.x; // 128 threads
    for (int i = tid; i < NODES * D; i += 128) sx[i] = x[(size_t)b * NODES * D + i];
    __syncthreads();
    if (tid < NODES) {
        float acc = gate_b[0];
#pragma unroll 8
        for (int d = 0; d < D; d++) acc = fmaf(sx[tid * D + d], gate_w[d], acc);
        sgate[tid] = 1.0f / (1.0f + expf(-acc));
    }
    __syncthreads();
    float pooled = 0.f;
#pragma unroll
    for (int n = 0; n < NODES; n++) pooled = fmaf(sx[n * D + tid], sgate[n], pooled);
    comb[tid]     = sx[11 * D + tid];
    comb[D + tid] = pooled;
    __syncthreads();
    float y = proj_b[tid];
#pragma unroll 8
    for (int c = 0; c < 2 * D; c++) y = fmaf(comb[c], proj_w[c * D + tid], y);
    float sum = y;
#pragma unroll
    for (int o = 16; o; o >>= 1) sum += __shfl_xor_sync(0xffffffffu, sum, o);
    if ((tid & 31) == 0) red[tid >> 5] = sum;
    __syncthreads();
    float mu = (red[0] + red[1] + red[2] + red[3]) * (1.0f / 128.0f);
    float c0 = y - mu;
    float cs = c0 * c0;
#pragma unroll
    for (int o = 16; o; o >>= 1) cs += __shfl_xor_sync(0xffffffffu, cs, o);
    __syncthreads();
    if ((tid & 31) == 0) red[tid >> 5] = cs;
    __syncthreads();
    float var = (red[0] + red[1] + red[2] + red[3]) * (1.0f / 128.0f);
    float yn = c0 * rsqrtf(var + 1e-5f) * pln_s[tid] + pln_b[tid];
    out[(size_t)b * D + tid] = gelu_exact(yn);
}

// ---------------- host orchestration ----------------
extern "C" void kernel_launch(void* const* d_in, const int* in_sizes, int n_in,
                              void* d_out, int out_size) {
    const float* patch   = (const float*)d_in[0];
    const float* band    = (const float*)d_in[1];
    const float* summ    = (const float*)d_in[2];
    const float* ln1_s   = (const float*)d_in[3];
    const float* ln1_b   = (const float*)d_in[4];
    const float* wq      = (const float*)d_in[5];
    const float* bq      = (const float*)d_in[6];
    const float* wk      = (const float*)d_in[7];
    const float* bk      = (const float*)d_in[8];
    const float* wv      = (const float*)d_in[9];
    const float* bv      = (const float*)d_in[10];
    const float* wo      = (const float*)d_in[11];
    const float* bo      = (const float*)d_in[12];
    const float* edge_b  = (const float*)d_in[13];
    const float* ln2_s   = (const float*)d_in[14];
    const float* ln2_b   = (const float*)d_in[15];
    const float* w1      = (const float*)d_in[16];
    const float* b1      = (const float*)d_in[17];
    const float* w2      = (const float*)d_in[18];
    const float* b2      = (const float*)d_in[19];
    const float* gate_w  = (const float*)d_in[20];
    const float* gate_b  = (const float*)d_in[21];
    const float* proj_w  = (const float*)d_in[22];
    const float* proj_b  = (const float*)d_in[23];
    const float* pln_s   = (const float*)d_in[24];
    const float* pln_b   = (const float*)d_in[25];
    float* out = (float*)d_out;

    float *x, *h, *qkv, *msg, *t, *wqkv, *bqkv;
    cudaGetSymbolAddress((void**)&x,    g_x);
    cudaGetSymbolAddress((void**)&h,    g_h);
    cudaGetSymbolAddress((void**)&qkv,  g_qkv);
    cudaGetSymbolAddress((void**)&msg,  g_msg);
    cudaGetSymbolAddress((void**)&t,    g_t);
    cudaGetSymbolAddress((void**)&wqkv, g_wqkv);
    cudaGetSymbolAddress((void**)&bqkv, g_bqkv);

    {
        int total = NTOK * D;
        init_x_kernel<<<(total + 255) / 256, 256>>>(patch, band, summ, x);
    }
    pack_qkv_kernel<<<(2 * D * 384 + 255) / 256, 256>>>(wq, wk, wv, bq, bk, bv, wqkv, bqkv);

    dim3 grid_qkv(3, NTOK / 64);   // N=384
    dim3 grid_d  (1, NTOK / 64);   // N=128
    dim3 grid_f  (4, NTOK / 64);   // N=512

    for (int l = 0; l < 2; l++) {
        const float* wo_l = wo + (size_t)l * D * D;
        const float* w1_l = w1 + (size_t)l * D * F;
        const float* w2_l = w2 + (size_t)l * F * D;

        ln_kernel<<<NTOK / 4, 128>>>(x, h, ln1_s + l * D, ln1_b + l * D);
        tgemm_kernel<<<grid_qkv, 256>>>(h, wqkv + (size_t)l * D * 384, bqkv + l * 384,
                                        qkv, nullptr, NTOK, 384, D, 0);
        attn_kernel<<<BATCH, 64>>>(qkv, edge_b + l * 36, msg);
        tgemm_kernel<<<grid_d, 256>>>(msg, wo_l, bo + l * D, x, x, NTOK, D, D, 1);
        ln_kernel<<<NTOK / 4, 128>>>(x, h, ln2_s + l * D, ln2_b + l * D);
        tgemm_kernel<<<grid_f, 256>>>(h, w1_l, b1 + l * F, t, nullptr, NTOK, F, D, 2);
        tgemm_kernel<<<grid_d, 256>>>(t, w2_l, b2 + l * D, x, x, NTOK, D, F, 1);
    }

    final_kernel<<<BATCH, 128>>>(x, gate_w, gate_b, proj_w, proj_b, pln_s, pln_b, out);
}

// round 3
// speedup vs baseline: 1.4233x; 1.1347x over previous
#include <cuda_runtime.h>
#include <cuda_bf16.h>
#include <math.h>
#include <stdint.h>

#define BATCH      2048
#define NODES      12
#define NTOK       (BATCH * NODES)     // 24576
#define D          128
#define F          512
#define NHEAD      4
#define DH         32
#define SCALE      0.17677669529663687f

typedef __nv_bfloat16 bf16;

// ---------------- scratch (device globals; no allocation) ----------------
__device__ float g_x   [NTOK * D];
__device__ float g_qkv [NTOK * 384];
__device__ __align__(16) bf16 g_hh[NTOK * D],  g_hl[NTOK * D];
__device__ __align__(16) bf16 g_mh[NTOK * D],  g_ml[NTOK * D];
__device__ __align__(16) bf16 g_th[NTOK * F],  g_tl[NTOK * F];
__device__ __align__(16) bf16 g_wqkvh[2 * 384 * D], g_wqkvl[2 * 384 * D]; // [l][n][k]
__device__ __align__(16) bf16 g_woh[2 * D * D],     g_wol[2 * D * D];
__device__ __align__(16) bf16 g_w1h[2 * F * D],     g_w1l[2 * F * D];
__device__ __align__(16) bf16 g_w2h[2 * D * F],     g_w2l[2 * D * F];
__device__ float g_bqkv[2 * 384];

__device__ __forceinline__ float gelu_exact(float x) {
    return 0.5f * x * (1.0f + erff(x * 0.7071067811865476f));
}
__device__ __forceinline__ void split_bf(float x, bf16& h, bf16& l) {
    h = __float2bfloat16(x);
    l = __float2bfloat16(x - __bfloat162float(h));
}
__device__ __forceinline__ void mma_bf16(float* c, const uint32_t* a, uint32_t b0, uint32_t b1) {
    asm volatile(
        "mma.sync.aligned.m16n8k16.row.col.f32.bf16.bf16.f32 "
        "{%0,%1,%2,%3}, {%4,%5,%6,%7}, {%8,%9}, {%0,%1,%2,%3};"
        : "+f"(c[0]), "+f"(c[1]), "+f"(c[2]), "+f"(c[3])
        : "r"(a[0]), "r"(a[1]), "r"(a[2]), "r"(a[3]), "r"(b0), "r"(b1));
}

// ---------------- init x ----------------
__global__ void init_x_kernel(const float* __restrict__ patch,
                              const float* __restrict__ band,
                              const float* __restrict__ summ,
                              float* __restrict__ x) {
    int idx = blockIdx.x * blockDim.x + threadIdx.x;
    if (idx >= NTOK * D) return;
    int d = idx & (D - 1);
    int row = idx >> 7;
    int node = row % NODES;
    int b = row / NODES;
    float val;
    if (node < 6)       val = patch[(b * 6 + node) * D + d];
    else if (node < 11) val = band [(b * 5 + (node - 6)) * D + d];
    else                val = summ[d];
    x[idx] = val;
}

// ---------------- weight packing: transpose + bf16 split ----------------
// src [2][Kd][Nd] -> out [2][Nd][Kd]
__global__ void pack_w_kernel(const float* __restrict__ src, bf16* __restrict__ oh,
                              bf16* __restrict__ ol, int Kd, int Nd) {
    int idx = blockIdx.x * 256 + threadIdx.x;
    int per = Kd * Nd;
    if (idx >= 2 * per) return;
    int l = idx / per, r = idx % per;
    int n = r / Kd, k = r % Kd;
    float v = src[(size_t)l * per + (size_t)k * Nd + n];
    split_bf(v, oh[idx], ol[idx]);
}
__global__ void pack_qkv_kernel(const float* __restrict__ wq, const float* __restrict__ wk,
                                const float* __restrict__ wv,
                                const float* __restrict__ bq, const float* __restrict__ bk,
                                const float* __restrict__ bv,
                                bf16* __restrict__ oh, bf16* __restrict__ ol,
                                float* __restrict__ bqkv) {
    int idx = blockIdx.x * 256 + threadIdx.x;
    if (idx < 2 * 384 * D) {
        int l = idx / (384 * D), r = idx % (384 * D);
        int n = r / D, k = r % D;
        const float* src = (n < 128) ? wq : ((n < 256) ? wk : wv);
        float v = src[(size_t)l * D * D + k * D + (n & 127)];
        split_bf(v, oh[idx], ol[idx]);
    }
    if (idx < 2 * 384) {
        int l = idx / 384, n = idx % 384;
        const float* sb = (n < 128) ? bq : ((n < 256) ? bk : bv);
        bqkv[idx] = sb[l * D + (n & 127)];
    }
}

// ---------------- LayerNorm + bf16 split output ----------------
__global__ void ln_split_kernel(const float* __restrict__ in, bf16* __restrict__ oh,
                                bf16* __restrict__ ol,
                                const float* __restrict__ s, const float* __restrict__ b) {
    int row  = blockIdx.x * 4 + (threadIdx.x >> 5);
    int lane = threadIdx.x & 31;
    const float* rp = in + (size_t)row * D;
    float v[4];
    float sum = 0.f;
#pragma unroll
    for (int i = 0; i < 4; i++) { v[i] = rp[lane + 32 * i]; sum += v[i]; }
#pragma unroll
    for (int o = 16; o; o >>= 1) sum += __shfl_xor_sync(0xffffffffu, sum, o);
    float mu = sum * (1.0f / 128.0f);
    float sq = 0.f;
#pragma unroll
    for (int i = 0; i < 4; i++) { float c = v[i] - mu; sq += c * c; }
#pragma unroll
    for (int o = 16; o; o >>= 1) sq += __shfl_xor_sync(0xffffffffu, sq, o);
    float inv = rsqrtf(sq * (1.0f / 128.0f) + 1e-5f);
#pragma unroll
    for (int i = 0; i < 4; i++) {
        int d = lane + 32 * i;
        float y = (v[i] - mu) * inv * s[d] + b[d];
        size_t o = (size_t)row * D + d;
        split_bf(y, oh[o], ol[o]);
    }
}

// ---------------- bf16x3 tensor-core GEMM ----------------
// C = epilogue(A @ W^T + bias); A split hi/lo bf16 [M][K], W split [N][K].
// BM=64 BN=128 BK=16, 256 threads, 8 warps of 32x32 tiles.
// mode 0: Cf = r;  mode 1: Cf = r + resid;  mode 2: split(gelu(r)) -> Ch/Cl
__global__ __launch_bounds__(256) void tgemm_kernel(
    const bf16* __restrict__ Ahg, const bf16* __restrict__ Alg,
    const bf16* __restrict__ Whg, const bf16* __restrict__ Wlg,
    const float* __restrict__ bias, float* __restrict__ Cf,
    bf16* __restrict__ Ch, bf16* __restrict__ Cl,
    const float* __restrict__ resid, int N, int K, int mode) {
    __shared__ uint32_t sAh[2][8][72], sAl[2][8][72];     // [buf][kpair][m]
    __shared__ uint32_t sWh[2][8][136], sWl[2][8][136];   // [buf][kpair][n]

    const int bm = blockIdx.y * 64;
    const int bn = blockIdx.x * 128;
    const int tid  = threadIdx.x;
    const int lane = tid & 31;
    const int wid  = tid >> 5;
    const int wm = (wid >> 2) << 5;
    const int wn = (wid & 3) << 5;
    const int g = lane >> 2, t = lane & 3;

    // gmem assignments
    const int ar = tid >> 2, act = tid & 3;      // A: row, pair-quad
    const int wr = tid >> 1, wct = tid & 1;      // W: n-row, half

    const bf16* Ahp = Ahg + (size_t)(bm + ar) * K + 4 * act;
    const bf16* Alp = Alg + (size_t)(bm + ar) * K + 4 * act;
    const bf16* Whp = Whg + (size_t)(bn + wr) * K + 8 * wct;
    const bf16* Wlp = Wlg + (size_t)(bn + wr) * K + 8 * wct;

    float acc[2][4][4];
#pragma unroll
    for (int i = 0; i < 2; i++)
#pragma unroll
        for (int j = 0; j < 4; j++)
#pragma unroll
            for (int c = 0; c < 4; c++) acc[i][j][c] = 0.f;

    uint2 pah = *(const uint2*)Ahp, pal = *(const uint2*)Alp;
    uint4 pwh = *(const uint4*)Whp, pwl = *(const uint4*)Wlp;

    {   // stage 0 stores
        int pc = act * 2;
        sAh[0][pc][ar] = pah.x; sAh[0][pc + 1][ar] = pah.y;
        sAl[0][pc][ar] = pal.x; sAl[0][pc + 1][ar] = pal.y;
        int qc = wct * 4;
        sWh[0][qc][wr] = pwh.x; sWh[0][qc + 1][wr] = pwh.y;
        sWh[0][qc + 2][wr] = pwh.z; sWh[0][qc + 3][wr] = pwh.w;
        sWl[0][qc][wr] = pwl.x; sWl[0][qc + 1][wr] = pwl.y;
        sWl[0][qc + 2][wr] = pwl.z; sWl[0][qc + 3][wr] = pwl.w;
    }
    __syncthreads();

    const int nstage = K >> 4;
    int buf = 0;
    for (int s = 0; s < nstage; s++) {
        if (s + 1 < nstage) {
            int off = (s + 1) << 4;
            pah = *(const uint2*)(Ahp + off);
            pal = *(const uint2*)(Alp + off);
            pwh = *(const uint4*)(Whp + off);
            pwl = *(const uint4*)(Wlp + off);
        }
        uint32_t ah[2][4], al[2][4], bh[4][2], bl[4][2];
#pragma unroll
        for (int mi = 0; mi < 2; mi++) {
            int m0 = wm + mi * 16 + g;
            ah[mi][0] = sAh[buf][t][m0];     ah[mi][1] = sAh[buf][t][m0 + 8];
            ah[mi][2] = sAh[buf][t + 4][m0]; ah[mi][3] = sAh[buf][t + 4][m0 + 8];
            al[mi][0] = sAl[buf][t][m0];     al[mi][1] = sAl[buf][t][m0 + 8];
            al[mi][2] = sAl[buf][t + 4][m0]; al[mi][3] = sAl[buf][t + 4][m0 + 8];
        }
#pragma unroll
        for (int ni = 0; ni < 4; ni++) {
            int n0 = wn + ni * 8 + g;
            bh[ni][0] = sWh[buf][t][n0]; bh[ni][1] = sWh[buf][t + 4][n0];
            bl[ni][0] = sWl[buf][t][n0]; bl[ni][1] = sWl[buf][t + 4][n0];
        }
#pragma unroll
        for (int mi = 0; mi < 2; mi++)
#pragma unroll
            for (int ni = 0; ni < 4; ni++) {
                mma_bf16(acc[mi][ni], ah[mi], bh[ni][0], bh[ni][1]);
                mma_bf16(acc[mi][ni], al[mi], bh[ni][0], bh[ni][1]);
                mma_bf16(acc[mi][ni], ah[mi], bl[ni][0], bl[ni][1]);
            }
        if (s + 1 < nstage) {
            int nb = buf ^ 1;
            int pc = act * 2;
            sAh[nb][pc][ar] = pah.x; sAh[nb][pc + 1][ar] = pah.y;
            sAl[nb][pc][ar] = pal.x; sAl[nb][pc + 1][ar] = pal.y;
            int qc = wct * 4;
            sWh[nb][qc][wr] = pwh.x; sWh[nb][qc + 1][wr] = pwh.y;
            sWh[nb][qc + 2][wr] = pwh.z; sWh[nb][qc + 3][wr] = pwh.w;
            sWl[nb][qc][wr] = pwl.x; sWl[nb][qc + 1][wr] = pwl.y;
            sWl[nb][qc + 2][wr] = pwl.z; sWl[nb][qc + 3][wr] = pwl.w;
            __syncthreads();
            buf = nb;
        }
    }

#pragma unroll
    for (int mi = 0; mi < 2; mi++) {
        int r0 = bm + wm + mi * 16 + g;
#pragma unroll
        for (int ni = 0; ni < 4; ni++) {
            int col = bn + wn + ni * 8 + 2 * t;
            float b0 = bias[col], b1 = bias[col + 1];
            float v0 = acc[mi][ni][0] + b0, v1 = acc[mi][ni][1] + b1;
            float v2 = acc[mi][ni][2] + b0, v3 = acc[mi][ni][3] + b1;
            size_t o0 = (size_t)r0 * N + col;
            size_t o1 = (size_t)(r0 + 8) * N + col;
            if (mode == 0) {
                *(float2*)&Cf[o0] = make_float2(v0, v1);
                *(float2*)&Cf[o1] = make_float2(v2, v3);
            } else if (mode == 1) {
                v0 += resid[o0]; v1 += resid[o0 + 1];
                v2 += resid[o1]; v3 += resid[o1 + 1];
                *(float2*)&Cf[o0] = make_float2(v0, v1);
                *(float2*)&Cf[o1] = make_float2(v2, v3);
            } else {
                v0 = gelu_exact(v0); v1 = gelu_exact(v1);
                v2 = gelu_exact(v2); v3 = gelu_exact(v3);
                bf16 h0, l0, h1, l1;
                split_bf(v0, h0, l0); split_bf(v1, h1, l1);
                __nv_bfloat162 hh, ll;
                hh.x = h0; hh.y = h1; ll.x = l0; ll.y = l1;
                *(__nv_bfloat162*)&Ch[o0] = hh;
                *(__nv_bfloat162*)&Cl[o0] = ll;
                split_bf(v2, h0, l0); split_bf(v3, h1, l1);
                hh.x = h0; hh.y = h1; ll.x = l0; ll.y = l1;
                *(__nv_bfloat162*)&Ch[o1] = hh;
                *(__nv_bfloat162*)&Cl[o1] = ll;
            }
        }
    }
}

// ---------------- dense 12-node attention; msg written as bf16 split ----------------
__global__ void attn_kernel(const float* __restrict__ qkv,
                            const float* __restrict__ edge_bias,
                            bf16* __restrict__ mh, bf16* __restrict__ ml) {
    __shared__ float sq[NODES * D], sk[NODES * D], sv[NODES * D];
    __shared__ float seb[36];
    int b = blockIdx.x;
    size_t base  = (size_t)b * NODES * 384;
    size_t obase = (size_t)b * NODES * D;
    for (int i = threadIdx.x; i < NODES * D; i += 64) {
        int node = i >> 7, col = i & 127;
        sq[i] = qkv[base + node * 384 + col];
        sk[i] = qkv[base + node * 384 + 128 + col];
        sv[i] = qkv[base + node * 384 + 256 + col];
    }
    if (threadIdx.x < 36) seb[threadIdx.x] = edge_bias[threadIdx.x];
    __syncthreads();
    int tt = threadIdx.x;
    if (tt < NODES * NHEAD) {
        int dst = tt >> 2, hd = tt & 3;
        int kd = dst < 6 ? 0 : (dst < 11 ? 1 : 2);
        float logits[NODES];
        float mx = -1e30f;
        const float* qp = &sq[dst * D + hd * DH];
#pragma unroll
        for (int j = 0; j < NODES; j++) {
            int ks = j < 6 ? 0 : (j < 11 ? 1 : 2);
            const float* kp = &sk[j * D + hd * DH];
            float dot = 0.f;
#pragma unroll
            for (int d = 0; d < DH; d++) dot = fmaf(qp[d], kp[d], dot);
            float lg = dot * SCALE + seb[(ks * 3 + kd) * NHEAD + hd];
            logits[j] = lg;
            mx = fmaxf(mx, lg);
        }
        float z = 0.f;
#pragma unroll
        for (int j = 0; j < NODES; j++) { logits[j] = expf(logits[j] - mx); z += logits[j]; }
        float inv = 1.0f / z;
        float out[DH] = {};
#pragma unroll
        for (int j = 0; j < NODES; j++) {
            float a = logits[j] * inv;
            const float* vp = &sv[j * D + hd * DH];
#pragma unroll
            for (int d = 0; d < DH; d++) out[d] = fmaf(a, vp[d], out[d]);
        }
#pragma unroll
        for (int d = 0; d < DH; d++) {
            size_t o = obase + dst * D + hd * DH + d;
            split_bf(out[d], mh[o], ml[o]);
        }
    }
}

// ---------------- final: gate/pool + proj + LN + gelu ----------------
__global__ void final_kernel(const float* __restrict__ x,
                             const float* __restrict__ gate_w, const float* __restrict__ gate_b,
                             const float* __restrict__ proj_w, const float* __restrict__ proj_b,
                             const float* __restrict__ pln_s, const float* __restrict__ pln_b,
                             float* __restrict__ out) {
    __shared__ float sx[NODES * D];
    __shared__ float sgate[NODES];
    __shared__ float comb[2 * D];
    __shared__ float red[4];
    int b = blockIdx.x, tid = threadIdx.x;
    for (int i = tid; i < NODES * D; i += 128) sx[i] = x[(size_t)b * NODES * D + i];
    __syncthreads();
    if (tid < NODES) {
        float acc = gate_b[0];
#pragma unroll 8
        for (int d = 0; d < D; d++) acc = fmaf(sx[tid * D + d], gate_w[d], acc);
        sgate[tid] = 1.0f / (1.0f + expf(-acc));
    }
    __syncthreads();
    float pooled = 0.f;
#pragma unroll
    for (int n = 0; n < NODES; n++) pooled = fmaf(sx[n * D + tid], sgate[n], pooled);
    comb[tid]     = sx[11 * D + tid];
    comb[D + tid] = pooled;
    __syncthreads();
    float y = proj_b[tid];
#pragma unroll 8
    for (int c = 0; c < 2 * D; c++) y = fmaf(comb[c], proj_w[c * D + tid], y);
    float sum = y;
#pragma unroll
    for (int o = 16; o; o >>= 1) sum += __shfl_xor_sync(0xffffffffu, sum, o);
    if ((tid & 31) == 0) red[tid >> 5] = sum;
    __syncthreads();
    float mu = (red[0] + red[1] + red[2] + red[3]) * (1.0f / 128.0f);
    float c0 = y - mu;
    float cs = c0 * c0;
#pragma unroll
    for (int o = 16; o; o >>= 1) cs += __shfl_xor_sync(0xffffffffu, cs, o);
    __syncthreads();
    if ((tid & 31) == 0) red[tid >> 5] = cs;
    __syncthreads();
    float var = (red[0] + red[1] + red[2] + red[3]) * (1.0f / 128.0f);
    float yn = c0 * rsqrtf(var + 1e-5f) * pln_s[tid] + pln_b[tid];
    out[(size_t)b * D + tid] = gelu_exact(yn);
}

// ---------------- host orchestration ----------------
extern "C" void kernel_launch(void* const* d_in, const int* in_sizes, int n_in,
                              void* d_out, int out_size) {
    const float* patch   = (const float*)d_in[0];
    const float* band    = (const float*)d_in[1];
    const float* summ    = (const float*)d_in[2];
    const float* ln1_s   = (const float*)d_in[3];
    const float* ln1_b   = (const float*)d_in[4];
    const float* wq      = (const float*)d_in[5];
    const float* bq      = (const float*)d_in[6];
    const float* wk      = (const float*)d_in[7];
    const float* bk      = (const float*)d_in[8];
    const float* wv      = (const float*)d_in[9];
    const float* bv      = (const float*)d_in[10];
    const float* wo      = (const float*)d_in[11];
    const float* bo      = (const float*)d_in[12];
    const float* edge_b  = (const float*)d_in[13];
    const float* ln2_s   = (const float*)d_in[14];
    const float* ln2_b   = (const float*)d_in[15];
    const float* w1      = (const float*)d_in[16];
    const float* b1      = (const float*)d_in[17];
    const float* w2      = (const float*)d_in[18];
    const float* b2      = (const float*)d_in[19];
    const float* gate_w  = (const float*)d_in[20];
    const float* gate_b  = (const float*)d_in[21];
    const float* proj_w  = (const float*)d_in[22];
    const float* proj_b  = (const float*)d_in[23];
    const float* pln_s   = (const float*)d_in[24];
    const float* pln_b   = (const float*)d_in[25];
    float* out = (float*)d_out;

    float *x, *qkv, *bqkv;
    bf16 *hh, *hl, *mh, *ml, *th, *tl;
    bf16 *wqkvh, *wqkvl, *woh, *wol, *w1h, *w1l, *w2h, *w2l;
    cudaGetSymbolAddress((void**)&x,     g_x);
    cudaGetSymbolAddress((void**)&qkv,   g_qkv);
    cudaGetSymbolAddress((void**)&bqkv,  g_bqkv);
    cudaGetSymbolAddress((void**)&hh,    g_hh);
    cudaGetSymbolAddress((void**)&hl,    g_hl);
    cudaGetSymbolAddress((void**)&mh,    g_mh);
    cudaGetSymbolAddress((void**)&ml,    g_ml);
    cudaGetSymbolAddress((void**)&th,    g_th);
    cudaGetSymbolAddress((void**)&tl,    g_tl);
    cudaGetSymbolAddress((void**)&wqkvh, g_wqkvh);
    cudaGetSymbolAddress((void**)&wqkvl, g_wqkvl);
    cudaGetSymbolAddress((void**)&woh,   g_woh);
    cudaGetSymbolAddress((void**)&wol,   g_wol);
    cudaGetSymbolAddress((void**)&w1h,   g_w1h);
    cudaGetSymbolAddress((void**)&w1l,   g_w1l);
    cudaGetSymbolAddress((void**)&w2h,   g_w2h);
    cudaGetSymbolAddress((void**)&w2l,   g_w2l);

    init_x_kernel<<<(NTOK * D + 255) / 256, 256>>>(patch, band, summ, x);
    pack_qkv_kernel<<<(2 * 384 * D + 255) / 256, 256>>>(wq, wk, wv, bq, bk, bv, wqkvh, wqkvl, bqkv);
    pack_w_kernel<<<(2 * D * D + 255) / 256, 256>>>(wo, woh, wol, D, D);
    pack_w_kernel<<<(2 * D * F + 255) / 256, 256>>>(w1, w1h, w1l, D, F);
    pack_w_kernel<<<(2 * F * D + 255) / 256, 256>>>(w2, w2h, w2l, F, D);

    dim3 grid_qkv(3, NTOK / 64);
    dim3 grid_d  (1, NTOK / 64);
    dim3 grid_f  (4, NTOK / 64);

    for (int l = 0; l < 2; l++) {
        ln_split_kernel<<<NTOK / 4, 128>>>(x, hh, hl, ln1_s + l * D, ln1_b + l * D);
        tgemm_kernel<<<grid_qkv, 256>>>(hh, hl, wqkvh + (size_t)l * 384 * D, wqkvl + (size_t)l * 384 * D,
                                        bqkv + l * 384, qkv, nullptr, nullptr, nullptr, 384, D, 0);
        attn_kernel<<<BATCH, 64>>>(qkv, edge_b + l * 36, mh, ml);
        tgemm_kernel<<<grid_d, 256>>>(mh, ml, woh + (size_t)l * D * D, wol + (size_t)l * D * D,
                                      bo + l * D, x, nullptr, nullptr, x, D, D, 1);
        ln_split_kernel<<<NTOK / 4, 128>>>(x, hh, hl, ln2_s + l * D, ln2_b + l * D);
        tgemm_kernel<<<grid_f, 256>>>(hh, hl, w1h + (size_t)l * F * D, w1l + (size_t)l * F * D,
                                      b1 + l * F, nullptr, th, tl, nullptr, F, D, 2);
        tgemm_kernel<<<grid_d, 256>>>(th, tl, w2h + (size_t)l * D * F, w2l + (size_t)l * D * F,
                                      b2 + l * D, x, nullptr, nullptr, x, D, F, 1);
    }

    final_kernel<<<BATCH, 128>>>(x, gate_w, gate_b, proj_w, proj_b, pln_s, pln_b, out);
}